// round 7
// baseline (speedup 1.0000x reference)
#include <cuda_runtime.h>
#include <cuda_bf16.h>

// high_order_residual (braq, order=2), row-wise over (11008, 4096).
// One CTA per row, 256 threads x 16 elements, single HBM pass.
// Mask is passed by the harness as int32 (one word per bool element).

#define ROW_LEN 4096
#define NTHREADS 256
#define CHUNKS 4          // float4/int4 chunks per thread (4*4 = 16 elems)

// Two-value block reduction. sb must be >= 18 floats, unique per call site
// (avoids WAR hazards between consecutive reductions).
__device__ __forceinline__ void block_reduce2(float& a, float& b, float* sb) {
#pragma unroll
    for (int o = 16; o > 0; o >>= 1) {
        a += __shfl_down_sync(0xFFFFFFFFu, a, o);
        b += __shfl_down_sync(0xFFFFFFFFu, b, o);
    }
    const int w = threadIdx.x >> 5;
    if ((threadIdx.x & 31) == 0) { sb[w] = a; sb[8 + w] = b; }
    __syncthreads();
    if (threadIdx.x == 0) {
        float ra = sb[0], rb = sb[8];
#pragma unroll
        for (int i = 1; i < 8; i++) { ra += sb[i]; rb += sb[8 + i]; }
        sb[16] = ra; sb[17] = rb;
    }
    __syncthreads();
    a = sb[16];
    b = sb[17];
}

__global__ __launch_bounds__(NTHREADS) void braq_order2_kernel(
    const float* __restrict__ x,
    const int* __restrict__ mask,     // one 32-bit word per element; nonzero = true
    float* __restrict__ out)
{
    __shared__ float sred[4][18];

    const int row = blockIdx.x;
    const int tid = threadIdx.x;
    const size_t base = (size_t)row * ROW_LEN;

    const float4* __restrict__ xp =
        reinterpret_cast<const float4*>(x + base);
    const int4* __restrict__ mp =
        reinterpret_cast<const int4*>(mask + base);

    float v[16];    // masked residual basis: xm, then residual1, then centered1
    float acc[16];  // scratch (centered0), then binary0*m
    float mf[16];   // mask as 0/1 float

    // ---- Load + first-pass stats: cnt, sum(xm) ----
    float cnt = 0.0f, s0 = 0.0f;
#pragma unroll
    for (int k = 0; k < CHUNKS; k++) {
        const int idx = tid + k * NTHREADS;
        const float4 xv = xp[idx];
        const int4 mw = mp[idx];
        const float m0 = mw.x ? 1.0f : 0.0f;
        const float m1 = mw.y ? 1.0f : 0.0f;
        const float m2 = mw.z ? 1.0f : 0.0f;
        const float m3 = mw.w ? 1.0f : 0.0f;
        mf[k * 4 + 0] = m0;
        mf[k * 4 + 1] = m1;
        mf[k * 4 + 2] = m2;
        mf[k * 4 + 3] = m3;
        v[k * 4 + 0] = xv.x * m0;
        v[k * 4 + 1] = xv.y * m1;
        v[k * 4 + 2] = xv.z * m2;
        v[k * 4 + 3] = xv.w * m3;
        cnt += m0 + m1 + m2 + m3;
        s0 += v[k * 4 + 0] + v[k * 4 + 1] + v[k * 4 + 2] + v[k * 4 + 3];
    }

    block_reduce2(cnt, s0, sred[0]);
    const float inv_cnt = 1.0f / fmaxf(cnt, 1.0f);
    const float mean0 = s0 * inv_cnt;   // 0 when cnt==0 (s0==0 too)

    // ---- Iteration 0: centered, |centered| reduction ----
    float a0 = 0.0f;
#pragma unroll
    for (int i = 0; i < 16; i++) {
        const float c = (v[i] - mean0) * mf[i];
        acc[i] = c;                      // stash centered0
        a0 += fabsf(c);
    }
    float dummy0 = 0.0f;
    block_reduce2(a0, dummy0, sred[1]);
    const float scale0 = a0 * inv_cnt;

    // ---- binary0, update residual, sum(residual1) ----
    float s1 = 0.0f;
#pragma unroll
    for (int i = 0; i < 16; i++) {
        const float c = acc[i];
        const float sg = (float)((c > 0.0f) - (c < 0.0f));
        const float b0m = (sg * scale0 + mean0) * mf[i];
        acc[i] = b0m;                    // binary0 * m (partial output)
        v[i] = v[i] - b0m;               // residual1 (0 outside mask)
        s1 += v[i];
    }
    float dummy1 = 0.0f;
    block_reduce2(s1, dummy1, sred[2]);
    const float mean1 = s1 * inv_cnt;

    // ---- Iteration 1: centered, |centered| reduction ----
    float a1 = 0.0f;
#pragma unroll
    for (int i = 0; i < 16; i++) {
        const float c = (v[i] - mean1) * mf[i];
        v[i] = c;                        // stash centered1
        a1 += fabsf(c);
    }
    float dummy2 = 0.0f;
    block_reduce2(a1, dummy2, sred[3]);
    const float scale1 = a1 * inv_cnt;

    // ---- binary1 + store ----
    float4* __restrict__ op = reinterpret_cast<float4*>(out + base);
#pragma unroll
    for (int k = 0; k < CHUNKS; k++) {
        const int idx = tid + k * NTHREADS;
        float4 o;
        {
            const float c = v[k * 4 + 0];
            const float sg = (float)((c > 0.0f) - (c < 0.0f));
            o.x = acc[k * 4 + 0] + (sg * scale1 + mean1) * mf[k * 4 + 0];
        }
        {
            const float c = v[k * 4 + 1];
            const float sg = (float)((c > 0.0f) - (c < 0.0f));
            o.y = acc[k * 4 + 1] + (sg * scale1 + mean1) * mf[k * 4 + 1];
        }
        {
            const float c = v[k * 4 + 2];
            const float sg = (float)((c > 0.0f) - (c < 0.0f));
            o.z = acc[k * 4 + 2] + (sg * scale1 + mean1) * mf[k * 4 + 2];
        }
        {
            const float c = v[k * 4 + 3];
            const float sg = (float)((c > 0.0f) - (c < 0.0f));
            o.w = acc[k * 4 + 3] + (sg * scale1 + mean1) * mf[k * 4 + 3];
        }
        op[idx] = o;
    }
}

extern "C" void kernel_launch(void* const* d_in, const int* in_sizes, int n_in,
                              void* d_out, int out_size) {
    const float* x = (const float*)d_in[0];
    const int* mask = (const int*)d_in[1];
    float* out = (float*)d_out;

    const int rows = in_sizes[0] / ROW_LEN;   // 11008
    braq_order2_kernel<<<rows, NTHREADS>>>(x, mask, out);
}